// round 12
// baseline (speedup 1.0000x reference)
#include <cuda_runtime.h>
#include <math_constants.h>

// Output spatial: 28x28, batch 8, out channels 256.
#define HW   28
#define NB   8
#define PLANE (HW*HW)        // 784
#define PLANE4 (PLANE/4)     // 196

// Pooled scratch (channel-tiling means we pool once, reuse across replicas).
__device__ float g_p1[NB*128*PLANE]; // pool2  of (8,128,56,56)
__device__ float g_p2[NB*64 *PLANE]; // pool4  of (8,64,112,112)
__device__ float g_p3[NB*32 *PLANE]; // pool8  of (8,32,224,224)
__device__ float g_p4[NB*16 *PLANE]; // pool16 of (8,16,448,448)

// Grid-wide arrival counter (returns to 0 at the end of every launch).
__device__ unsigned g_count;

// Block-range dispatch (256 threads/block). All requests lane-contiguous
// (100% sector efficiency). Combine blocks trail the grid and spin on g_count.
#define A_BLOCKS 12544   // k=16, t4, warp/output, 2 loads (64B runs)
#define B_BLOCKS 6272    // k=8,  t3, warp/4 outputs, 2 loads (32B runs)
#define C_BLOCKS 1568    // k=4,  t2, thread/output, 4 row-loads
#define D_BLOCKS 1568    // k=2,  t1, thread/2 outputs, 2 row-loads
#define POOL_BLOCKS (A_BLOCKS + B_BLOCKS + C_BLOCKS + D_BLOCKS)
#define COMB_BLOCKS 784  // 784*256 threads * 2 float4-outputs = full output
#define TOTAL_BLOCKS (POOL_BLOCKS + COMB_BLOCKS)

__device__ __forceinline__ float max4(float4 v) {
    return fmaxf(fmaxf(v.x, v.y), fmaxf(v.z, v.w));
}

__global__ void __launch_bounds__(256) fused_all_kernel(
    const float* __restrict__ t1, const float* __restrict__ t2,
    const float* __restrict__ t3, const float* __restrict__ t4,
    const float* __restrict__ ff, float* __restrict__ out)
{
    int bid = blockIdx.x;
    int tid = threadIdx.x;

    if (bid < POOL_BLOCKS) {
        // ================= POOL PHASE =================
        if (bid < A_BLOCKS) {
            // ---- k=16 pool of (8,16,448,448): one warp per output ----
            // Lane l: 16B chunk (l&3) of rows (l>>2) and (l>>2)+8. 64B dense runs.
            int t = bid * 256 + tid;
            int oidx = t >> 5;                    // 0..100351
            int lane = t & 31;
            int r  = lane >> 2;
            int ch = lane & 3;
            int w = oidx % HW;
            int h = (oidx / HW) % HW;
            long bc = oidx / PLANE;               // b*16 + c
            const float* base = t4 + (bc * 448 + (long)(h * 16 + r)) * 448
                                   + (long)w * 16 + ch * 4;
            float4 v0 = __ldcs(reinterpret_cast<const float4*>(base));
            float4 v1 = __ldcs(reinterpret_cast<const float4*>(base + 8L * 448));
            float m = fmaxf(max4(v0), max4(v1));
            #pragma unroll
            for (int k = 16; k >= 1; k >>= 1)
                m = fmaxf(m, __shfl_xor_sync(0xffffffffu, m, k));
            if (lane == 0) g_p4[oidx] = m;
        } else if (bid < A_BLOCKS + B_BLOCKS) {
            // ---- k=8 pool of (8,32,224,224): warp covers 4 outputs ----
            int t = (bid - A_BLOCKS) * 256 + tid;
            int obase = (t >> 5) * 4;
            int lane = t & 31;
            int h2 = lane >> 4;                   // 0 or 1
            int ll = lane & 15;
            int r  = ll >> 1;
            int ch = ll & 1;
            int o0 = obase + h2;                  // second output is o0+2
            int w = o0 % HW;                      // 28 % 4 == 0: shared h,bc
            int h = (o0 / HW) % HW;
            long bc = o0 / PLANE;                 // b*32 + c
            const float* base = t3 + (bc * 224 + (long)(h * 8 + r)) * 224
                                   + (long)w * 8 + ch * 4;
            float4 v0 = __ldcs(reinterpret_cast<const float4*>(base));
            float4 v1 = __ldcs(reinterpret_cast<const float4*>(base + 16));
            float m0 = max4(v0);
            float m1 = max4(v1);
            #pragma unroll
            for (int k = 8; k >= 1; k >>= 1) {
                m0 = fmaxf(m0, __shfl_xor_sync(0xffffffffu, m0, k));
                m1 = fmaxf(m1, __shfl_xor_sync(0xffffffffu, m1, k));
            }
            if (ll == 0) {
                g_p3[o0]     = m0;
                g_p3[o0 + 2] = m1;
            }
        } else if (bid < A_BLOCKS + B_BLOCKS + C_BLOCKS) {
            // ---- k=4 pool of (8,64,112,112): thread per output ----
            int oidx = (bid - A_BLOCKS - B_BLOCKS) * 256 + tid;
            int w = oidx % HW;
            int h = (oidx / HW) % HW;
            long bc = oidx / PLANE;               // b*64 + c
            const float* p = t2 + (bc * 112 + (long)(h * 4)) * 112 + (long)w * 4;
            float4 v0 = __ldcs(reinterpret_cast<const float4*>(p));
            float4 v1 = __ldcs(reinterpret_cast<const float4*>(p + 112));
            float4 v2 = __ldcs(reinterpret_cast<const float4*>(p + 224));
            float4 v3 = __ldcs(reinterpret_cast<const float4*>(p + 336));
            g_p2[oidx] = fmaxf(fmaxf(max4(v0), max4(v1)), fmaxf(max4(v2), max4(v3)));
        } else {
            // ---- k=2 pool of (8,128,56,56): thread per 2 outputs ----
            int pi = (bid - A_BLOCKS - B_BLOCKS - C_BLOCKS) * 256 + tid;
            constexpr int HALFROW = HW / 2;       // 14
            constexpr int PPLANE = PLANE / 2;     // 392
            int w2 = pi % HALFROW;
            int h  = (pi / HALFROW) % HW;
            long bc = pi / PPLANE;                // b*128 + c
            const float* p = t1 + (bc * 56 + (long)(h * 2)) * 56 + (long)w2 * 4;
            float4 a = __ldcs(reinterpret_cast<const float4*>(p));
            float4 b = __ldcs(reinterpret_cast<const float4*>(p + 56));
            float2 o;
            o.x = fmaxf(fmaxf(a.x, a.y), fmaxf(b.x, b.y));
            o.y = fmaxf(fmaxf(a.z, a.w), fmaxf(b.z, b.w));
            *reinterpret_cast<float2*>(g_p1 + bc * PLANE + h * HW + w2 * 2) = o;
        }

        // Release scratch writes, then arrive.
        __threadfence();
        __syncthreads();
        if (tid == 0) atomicAdd(&g_count, 1u);
        return;
    }

    // ================= COMBINE PHASE (trailing blocks) =================
    constexpr int TOTAL4 = NB * 256 * PLANE4;   // 401408
    constexpr int HALF4  = TOTAL4 / 2;          // 200704
    int idx4 = (bid - POOL_BLOCKS) * 256 + tid; // < HALF4 exactly

    int s = idx4 % PLANE4;
    int c = (idx4 / PLANE4) % 256;
    int b = idx4 / (PLANE4 * 256);              // 0..3; second element is b+4

    const float4* P1 = reinterpret_cast<const float4*>(g_p1);
    const float4* P2 = reinterpret_cast<const float4*>(g_p2);
    const float4* P3 = reinterpret_cast<const float4*>(g_p3);
    const float4* P4 = reinterpret_cast<const float4*>(g_p4);
    const float4* FF = reinterpret_cast<const float4*>(ff);

    int i1 = (b * 128 + (c & 127)) * PLANE4 + s;
    int i2 = (b * 64  + (c & 63))  * PLANE4 + s;
    int i3 = (b * 32  + (c & 31))  * PLANE4 + s;
    int i4 = (b * 16  + (c & 15))  * PLANE4 + s;

    // Preload ff (independent of pool) BEFORE the spin: its DRAM latency
    // overlaps the pool tail instead of serializing after it.
    float4 f0 = __ldcs(FF + idx4);
    float4 f1 = __ldcs(FF + idx4 + HALF4);

    // Wait for all pool blocks.
    if (tid == 0) {
        volatile unsigned* vc = &g_count;
        while (*vc < POOL_BLOCKS) { }
    }
    __syncthreads();
    __threadfence();   // acquire: order scratch reads after the flag

    float4 a0 = P1[i1],  a1 = P1[i1 + 4*128*PLANE4];
    float4 d0 = P2[i2],  d1 = P2[i2 + 4*64 *PLANE4];
    float4 e0 = P3[i3],  e1 = P3[i3 + 4*32 *PLANE4];
    float4 g0 = P4[i4],  g1 = P4[i4 + 4*16 *PLANE4];

    float4 o0, o1;
    o0.x = fmaxf(a0.x + d0.x + e0.x + g0.x + f0.x, 0.0f);
    o0.y = fmaxf(a0.y + d0.y + e0.y + g0.y + f0.y, 0.0f);
    o0.z = fmaxf(a0.z + d0.z + e0.z + g0.z + f0.z, 0.0f);
    o0.w = fmaxf(a0.w + d0.w + e0.w + g0.w + f0.w, 0.0f);
    o1.x = fmaxf(a1.x + d1.x + e1.x + g1.x + f1.x, 0.0f);
    o1.y = fmaxf(a1.y + d1.y + e1.y + g1.y + f1.y, 0.0f);
    o1.z = fmaxf(a1.z + d1.z + e1.z + g1.z + f1.z, 0.0f);
    o1.w = fmaxf(a1.w + d1.w + e1.w + g1.w + f1.w, 0.0f);
    reinterpret_cast<float4*>(out)[idx4] = o0;
    reinterpret_cast<float4*>(out)[idx4 + HALF4] = o1;

    // Arrive; the final arriver (necessarily a combine block) resets the
    // counter to 0 so every launch starts from the same state.
    __syncthreads();
    if (tid == 0) {
        unsigned old = atomicAdd(&g_count, 1u);
        if (old == TOTAL_BLOCKS - 1) atomicExch(&g_count, 0u);
    }
}

extern "C" void kernel_launch(void* const* d_in, const int* in_sizes, int n_in,
                              void* d_out, int out_size) {
    // Map inputs by unique element count (robust to ordering).
    const float *t1 = nullptr, *t2 = nullptr, *t3 = nullptr, *t4 = nullptr, *ff = nullptr;
    for (int i = 0; i < n_in; i++) {
        switch (in_sizes[i]) {
            case 8*128*56*56:   t1 = (const float*)d_in[i]; break;   // 3211264
            case 8*64*112*112:  t2 = (const float*)d_in[i]; break;   // 6422528
            case 8*32*224*224:  t3 = (const float*)d_in[i]; break;   // 12845056
            case 8*16*448*448:  t4 = (const float*)d_in[i]; break;   // 25690112
            case 8*256*28*28:   ff = (const float*)d_in[i]; break;   // 1605632
        }
    }

    fused_all_kernel<<<TOTAL_BLOCKS, 256>>>(t1, t2, t3, t4, ff, (float*)d_out);
}

// round 14
// speedup vs baseline: 1.2376x; 1.2376x over previous
#include <cuda_runtime.h>
#include <math_constants.h>

// Output spatial: 28x28, batch 8, out channels 256.
#define HW   28
#define NB   8
#define PLANE (HW*HW)        // 784
#define PLANE4 (PLANE/4)     // 196

// Pooled scratch (channel-tiling means we pool once, reuse across replicas).
__device__ float g_p1[NB*128*PLANE]; // pool2  of (8,128,56,56)
__device__ float g_p2[NB*64 *PLANE]; // pool4  of (8,64,112,112)
__device__ float g_p3[NB*32 *PLANE]; // pool8  of (8,32,224,224)
__device__ float g_p4[NB*16 *PLANE]; // pool16 of (8,16,448,448)

// Grid-wide barrier counters (self-reset at the end of every launch).
__device__ unsigned g_arrive;
__device__ unsigned g_done;

// Pool work-unit ranges (unit = one thread's slice; same lane-contiguous
// mappings as the 39.0us two-kernel version). All boundaries are multiples
// of 256, so a warp/block never straddles segments.
#define A_UNITS (100352*32)          // k=16: warp/output      = 3211264
#define B_UNITS (200704*8)           // k=8 : warp/4 outputs   = 1605632
#define C_UNITS 401408               // k=4 : thread/output
#define D_UNITS 401408               // k=2 : thread/2 outputs
#define AB_END  (A_UNITS + B_UNITS)             // 4816896
#define ABC_END (AB_END + C_UNITS)              // 5218304
#define TOTALU  (ABC_END + D_UNITS)             // 5619712
#define TOTAL4  (NB * 256 * PLANE4)             // 401408 combine items

__device__ __forceinline__ float max4(float4 v) {
    return fmaxf(fmaxf(v.x, v.y), fmaxf(v.z, v.w));
}

__global__ void __launch_bounds__(256, 8) persist_kernel(
    const float* __restrict__ t1, const float* __restrict__ t2,
    const float* __restrict__ t3, const float* __restrict__ t4,
    const float* __restrict__ ff, float* __restrict__ out)
{
    int tid = threadIdx.x;
    int gid = blockIdx.x * 256 + tid;
    int nth = gridDim.x * 256;

    // ================= POOL PHASE (grid-stride over units) =================
    for (int u = gid; u < TOTALU; u += nth) {
        if (u < A_UNITS) {
            // ---- k=16 pool of (8,16,448,448): one warp per output ----
            // Lane l: 16B chunk (l&3) of rows (l>>2), (l>>2)+8. 64B dense runs.
            int oidx = u >> 5;
            int lane = u & 31;
            int r  = lane >> 2;
            int ch = lane & 3;
            int w = oidx % HW;
            int h = (oidx / HW) % HW;
            long bc = oidx / PLANE;               // b*16 + c
            const float* base = t4 + (bc * 448 + (long)(h * 16 + r)) * 448
                                   + (long)w * 16 + ch * 4;
            float4 v0 = __ldcs(reinterpret_cast<const float4*>(base));
            float4 v1 = __ldcs(reinterpret_cast<const float4*>(base + 8L * 448));
            float m = fmaxf(max4(v0), max4(v1));
            #pragma unroll
            for (int k = 16; k >= 1; k >>= 1)
                m = fmaxf(m, __shfl_xor_sync(0xffffffffu, m, k));
            if (lane == 0) g_p4[oidx] = m;
        } else if (u < AB_END) {
            // ---- k=8 pool of (8,32,224,224): warp covers 4 outputs ----
            int t = u - A_UNITS;
            int obase = (t >> 5) * 4;
            int lane = t & 31;
            int h2 = lane >> 4;                   // 0 or 1
            int ll = lane & 15;
            int r  = ll >> 1;
            int ch = ll & 1;
            int o0 = obase + h2;                  // second output is o0+2
            int w = o0 % HW;                      // 28 % 4 == 0: shared h,bc
            int h = (o0 / HW) % HW;
            long bc = o0 / PLANE;                 // b*32 + c
            const float* base = t3 + (bc * 224 + (long)(h * 8 + r)) * 224
                                   + (long)w * 8 + ch * 4;
            float4 v0 = __ldcs(reinterpret_cast<const float4*>(base));
            float4 v1 = __ldcs(reinterpret_cast<const float4*>(base + 16));
            float m0 = max4(v0);
            float m1 = max4(v1);
            #pragma unroll
            for (int k = 8; k >= 1; k >>= 1) {
                m0 = fmaxf(m0, __shfl_xor_sync(0xffffffffu, m0, k));
                m1 = fmaxf(m1, __shfl_xor_sync(0xffffffffu, m1, k));
            }
            if (ll == 0) {
                g_p3[o0]     = m0;
                g_p3[o0 + 2] = m1;
            }
        } else if (u < ABC_END) {
            // ---- k=4 pool of (8,64,112,112): thread per output ----
            int oidx = u - AB_END;
            int w = oidx % HW;
            int h = (oidx / HW) % HW;
            long bc = oidx / PLANE;               // b*64 + c
            const float* p = t2 + (bc * 112 + (long)(h * 4)) * 112 + (long)w * 4;
            float4 v0 = __ldcs(reinterpret_cast<const float4*>(p));
            float4 v1 = __ldcs(reinterpret_cast<const float4*>(p + 112));
            float4 v2 = __ldcs(reinterpret_cast<const float4*>(p + 224));
            float4 v3 = __ldcs(reinterpret_cast<const float4*>(p + 336));
            g_p2[oidx] = fmaxf(fmaxf(max4(v0), max4(v1)), fmaxf(max4(v2), max4(v3)));
        } else {
            // ---- k=2 pool of (8,128,56,56): thread per 2 outputs ----
            int pi = u - ABC_END;
            constexpr int HALFROW = HW / 2;       // 14
            constexpr int PPLANE = PLANE / 2;     // 392
            int w2 = pi % HALFROW;
            int h  = (pi / HALFROW) % HW;
            long bc = pi / PPLANE;                // b*128 + c
            const float* p = t1 + (bc * 56 + (long)(h * 2)) * 56 + (long)w2 * 4;
            float4 a = __ldcs(reinterpret_cast<const float4*>(p));
            float4 b = __ldcs(reinterpret_cast<const float4*>(p + 56));
            float2 o;
            o.x = fmaxf(fmaxf(a.x, a.y), fmaxf(b.x, b.y));
            o.y = fmaxf(fmaxf(a.z, a.w), fmaxf(b.z, b.w));
            *reinterpret_cast<float2*>(g_p1 + bc * PLANE + h * HW + w2 * 2) = o;
        }
    }

    // ---- Prefetch ff into smem (overlaps the pool tail / barrier wait). ----
    // Each thread only ever touches its own smem slots: no extra sync needed.
    __shared__ float4 s_ff[2][256];
    const float4* FF = reinterpret_cast<const float4*>(ff);
    int v0i = gid;
    int v1i = gid + nth;
    if (v0i < TOTAL4) s_ff[0][tid] = __ldcs(FF + v0i);
    if (v1i < TOTAL4) s_ff[1][tid] = __ldcs(FF + v1i);

    // ================= GRID BARRIER =================
    __threadfence();                 // release scratch writes
    __syncthreads();                 // all warps of block done before arrive
    if (tid == 0) {
        atomicAdd(&g_arrive, 1u);
        while (*(volatile unsigned*)&g_arrive < gridDim.x) __nanosleep(32);
    }
    __syncthreads();
    __threadfence();                 // acquire before reading scratch

    // ================= COMBINE PHASE =================
    const float4* P1 = reinterpret_cast<const float4*>(g_p1);
    const float4* P2 = reinterpret_cast<const float4*>(g_p2);
    const float4* P3 = reinterpret_cast<const float4*>(g_p3);
    const float4* P4 = reinterpret_cast<const float4*>(g_p4);

    #pragma unroll
    for (int j = 0; j < 2; j++) {
        int v = gid + j * nth;
        if (v >= TOTAL4) break;
        int s = v % PLANE4;
        int c = (v / PLANE4) & 255;
        int b = v / (PLANE4 * 256);

        float4 a = P1[(b * 128 + (c & 127)) * PLANE4 + s];
        float4 d = P2[(b * 64  + (c & 63))  * PLANE4 + s];
        float4 e = P3[(b * 32  + (c & 31))  * PLANE4 + s];
        float4 g = P4[(b * 16  + (c & 15))  * PLANE4 + s];
        float4 f = s_ff[j][tid];

        float4 o;
        o.x = fmaxf(a.x + d.x + e.x + g.x + f.x, 0.0f);
        o.y = fmaxf(a.y + d.y + e.y + g.y + f.y, 0.0f);
        o.z = fmaxf(a.z + d.z + e.z + g.z + f.z, 0.0f);
        o.w = fmaxf(a.w + d.w + e.w + g.w + f.w, 0.0f);
        reinterpret_cast<float4*>(out)[v] = o;
    }

    // ---- Completion count; last block resets both counters for replay. ----
    __syncthreads();
    if (tid == 0) {
        unsigned old = atomicAdd(&g_done, 1u);
        if (old == gridDim.x - 1) {
            g_arrive = 0;
            g_done = 0;
            __threadfence();
        }
    }
}

extern "C" void kernel_launch(void* const* d_in, const int* in_sizes, int n_in,
                              void* d_out, int out_size) {
    // Map inputs by unique element count (robust to ordering).
    const float *t1 = nullptr, *t2 = nullptr, *t3 = nullptr, *t4 = nullptr, *ff = nullptr;
    for (int i = 0; i < n_in; i++) {
        switch (in_sizes[i]) {
            case 8*128*56*56:   t1 = (const float*)d_in[i]; break;   // 3211264
            case 8*64*112*112:  t2 = (const float*)d_in[i]; break;   // 6422528
            case 8*32*224*224:  t3 = (const float*)d_in[i]; break;   // 12845056
            case 8*16*448*448:  t4 = (const float*)d_in[i]; break;   // 25690112
            case 8*256*28*28:   ff = (const float*)d_in[i]; break;   // 1605632
        }
    }

    // Exactly one resident wave: SMs x 8 blocks of 256 threads
    // (__launch_bounds__(256,8) caps regs at 32 -> residency guaranteed).
    int dev = 0, sms = 0;
    cudaGetDevice(&dev);
    cudaDeviceGetAttribute(&sms, cudaDevAttrMultiProcessorCount, dev);
    if (sms <= 0) sms = 148;
    int grid = sms * 8;

    persist_kernel<<<grid, 256>>>(t1, t2, t3, t4, ff, (float*)d_out);
}

// round 15
// speedup vs baseline: 1.3578x; 1.0971x over previous
#include <cuda_runtime.h>
#include <math_constants.h>

// Output spatial: 28x28, batch 8, out channels 256.
#define HW   28
#define NB   8
#define PLANE (HW*HW)        // 784
#define PLANE4 (PLANE/4)     // 196

// Pooled scratch (channel-tiling means we pool once, reuse across replicas).
__device__ float g_p1[NB*128*PLANE]; // pool2  of (8,128,56,56)
__device__ float g_p2[NB*64 *PLANE]; // pool4  of (8,64,112,112)
__device__ float g_p3[NB*32 *PLANE]; // pool8  of (8,32,224,224)
__device__ float g_p4[NB*16 *PLANE]; // pool16 of (8,16,448,448)

// Block-range dispatch (256 threads/block). All requests lane-contiguous
// (100% sector efficiency): consecutive lanes read consecutive 16B.
#define A_BLOCKS 12544   // k=16, t4, warp/output, 2 loads (64B runs)
#define B_BLOCKS 6272    // k=8,  t3, warp/4 outputs, 2 loads (32B runs)
#define C_BLOCKS 1568    // k=4,  t2, thread/output, 4 row-loads
#define D_BLOCKS 1568    // k=2,  t1, thread/2 outputs, 2 row-loads
#define POOL_BLOCKS (A_BLOCKS + B_BLOCKS + C_BLOCKS + D_BLOCKS)

__device__ __forceinline__ float max4(float4 v) {
    return fmaxf(fmaxf(v.x, v.y), fmaxf(v.z, v.w));
}

__global__ void __launch_bounds__(256) fused_pool_kernel(
    const float* __restrict__ t1, const float* __restrict__ t2,
    const float* __restrict__ t3, const float* __restrict__ t4)
{
    // Allow the dependent (combine) kernel to begin dispatching into freed
    // block slots immediately; its gridsync still waits for our completion.
    cudaTriggerProgrammaticLaunchCompletion();

    int bid = blockIdx.x;
    int tid = threadIdx.x;

    if (bid < A_BLOCKS) {
        // ---- k=16 pool of (8,16,448,448): one warp per output ----
        // Lane l: 16B chunk (l&3) of rows (l>>2) and (l>>2)+8. 64B dense runs.
        int t = bid * 256 + tid;
        int oidx = t >> 5;                        // 0..100351
        int lane = t & 31;
        int r  = lane >> 2;                       // 0..7
        int ch = lane & 3;                        // 0..3
        int w = oidx % HW;
        int h = (oidx / HW) % HW;
        long bc = oidx / PLANE;                   // b*16 + c
        const float* base = t4 + (bc * 448 + (long)(h * 16 + r)) * 448
                               + (long)w * 16 + ch * 4;
        float4 v0 = __ldcs(reinterpret_cast<const float4*>(base));
        float4 v1 = __ldcs(reinterpret_cast<const float4*>(base + 8L * 448));
        float m = fmaxf(max4(v0), max4(v1));
        #pragma unroll
        for (int k = 16; k >= 1; k >>= 1)
            m = fmaxf(m, __shfl_xor_sync(0xffffffffu, m, k));
        if (lane == 0) g_p4[oidx] = m;
        return;
    }
    bid -= A_BLOCKS;

    if (bid < B_BLOCKS) {
        // ---- k=8 pool of (8,32,224,224): warp covers 4 outputs ----
        int t = bid * 256 + tid;
        int obase = (t >> 5) * 4;                 // multiple of 4
        int lane = t & 31;
        int h2 = lane >> 4;                       // 0 or 1
        int ll = lane & 15;
        int r  = ll >> 1;                         // 0..7
        int ch = ll & 1;                          // 0..1
        int o0 = obase + h2;                      // second output is o0+2
        int w = o0 % HW;                          // 28 % 4 == 0: shared h,bc
        int h = (o0 / HW) % HW;
        long bc = o0 / PLANE;                     // b*32 + c
        const float* base = t3 + (bc * 224 + (long)(h * 8 + r)) * 224
                               + (long)w * 8 + ch * 4;
        float4 v0 = __ldcs(reinterpret_cast<const float4*>(base));       // o0
        float4 v1 = __ldcs(reinterpret_cast<const float4*>(base + 16));  // o0+2
        float m0 = max4(v0);
        float m1 = max4(v1);
        #pragma unroll
        for (int k = 8; k >= 1; k >>= 1) {        // reduce within 16-lane group
            m0 = fmaxf(m0, __shfl_xor_sync(0xffffffffu, m0, k));
            m1 = fmaxf(m1, __shfl_xor_sync(0xffffffffu, m1, k));
        }
        if (ll == 0) {
            g_p3[o0]     = m0;
            g_p3[o0 + 2] = m1;
        }
        return;
    }
    bid -= B_BLOCKS;

    if (bid < C_BLOCKS) {
        // ---- k=4 pool of (8,64,112,112): thread per output, 4 row-loads ----
        int oidx = bid * 256 + tid;               // 0..401407
        int w = oidx % HW;
        int h = (oidx / HW) % HW;
        long bc = oidx / PLANE;                   // b*64 + c
        const float* p = t2 + (bc * 112 + (long)(h * 4)) * 112 + (long)w * 4;
        float4 v0 = __ldcs(reinterpret_cast<const float4*>(p));
        float4 v1 = __ldcs(reinterpret_cast<const float4*>(p + 112));
        float4 v2 = __ldcs(reinterpret_cast<const float4*>(p + 224));
        float4 v3 = __ldcs(reinterpret_cast<const float4*>(p + 336));
        g_p2[oidx] = fmaxf(fmaxf(max4(v0), max4(v1)), fmaxf(max4(v2), max4(v3)));
        return;
    }
    bid -= C_BLOCKS;

    {
        // ---- k=2 pool of (8,128,56,56): thread per 2 horizontal outputs ----
        int pi = bid * 256 + tid;                 // 0..401407 (output pairs)
        constexpr int HALFROW = HW / 2;           // 14 pairs per output row
        constexpr int PPLANE = PLANE / 2;         // 392 pairs per plane
        int w2 = pi % HALFROW;
        int h  = (pi / HALFROW) % HW;
        long bc = pi / PPLANE;                    // b*128 + c
        const float* p = t1 + (bc * 56 + (long)(h * 2)) * 56 + (long)w2 * 4;
        float4 a = __ldcs(reinterpret_cast<const float4*>(p));
        float4 b = __ldcs(reinterpret_cast<const float4*>(p + 56));
        float2 o;
        o.x = fmaxf(fmaxf(a.x, a.y), fmaxf(b.x, b.y));
        o.y = fmaxf(fmaxf(a.z, a.w), fmaxf(b.z, b.w));
        *reinterpret_cast<float2*>(g_p1 + bc * PLANE + h * HW + w2 * 2) = o;
    }
}

__global__ void __launch_bounds__(256) combine_kernel(
    const float* __restrict__ ff, float* __restrict__ out)
{
    constexpr int TOTAL4 = NB * 256 * PLANE4;   // 401408
    constexpr int HALF4  = TOTAL4 / 2;          // 200704 (= 4 batches worth)
    int idx4 = blockIdx.x * blockDim.x + threadIdx.x;   // grid covers HALF4

    int s = idx4 % PLANE4;
    int c = (idx4 / PLANE4) % 256;
    int b = idx4 / (PLANE4 * 256);              // 0..3; second element is b+4

    const float4* P1 = reinterpret_cast<const float4*>(g_p1);
    const float4* P2 = reinterpret_cast<const float4*>(g_p2);
    const float4* P3 = reinterpret_cast<const float4*>(g_p3);
    const float4* P4 = reinterpret_cast<const float4*>(g_p4);
    const float4* FF = reinterpret_cast<const float4*>(ff);

    int i1 = (b * 128 + (c & 127)) * PLANE4 + s;
    int i2 = (b * 64  + (c & 63))  * PLANE4 + s;
    int i3 = (b * 32  + (c & 31))  * PLANE4 + s;
    int i4 = (b * 16  + (c & 15))  * PLANE4 + s;

    // PDL preamble: load ff (independent of the pool kernel's output) while
    // the pool kernel is still draining.
    float4 f0 = __ldcs(FF + idx4);
    float4 f1 = __ldcs(FF + idx4 + HALF4);

    // Wait for the pool kernel's writes to be visible.
    cudaGridDependencySynchronize();

    float4 a0 = P1[i1],  a1 = P1[i1 + 4*128*PLANE4];
    float4 d0 = P2[i2],  d1 = P2[i2 + 4*64 *PLANE4];
    float4 e0 = P3[i3],  e1 = P3[i3 + 4*32 *PLANE4];
    float4 g0 = P4[i4],  g1 = P4[i4 + 4*16 *PLANE4];

    float4 o0, o1;
    o0.x = fmaxf(a0.x + d0.x + e0.x + g0.x + f0.x, 0.0f);
    o0.y = fmaxf(a0.y + d0.y + e0.y + g0.y + f0.y, 0.0f);
    o0.z = fmaxf(a0.z + d0.z + e0.z + g0.z + f0.z, 0.0f);
    o0.w = fmaxf(a0.w + d0.w + e0.w + g0.w + f0.w, 0.0f);
    o1.x = fmaxf(a1.x + d1.x + e1.x + g1.x + f1.x, 0.0f);
    o1.y = fmaxf(a1.y + d1.y + e1.y + g1.y + f1.y, 0.0f);
    o1.z = fmaxf(a1.z + d1.z + e1.z + g1.z + f1.z, 0.0f);
    o1.w = fmaxf(a1.w + d1.w + e1.w + g1.w + f1.w, 0.0f);
    reinterpret_cast<float4*>(out)[idx4] = o0;
    reinterpret_cast<float4*>(out)[idx4 + HALF4] = o1;
}

extern "C" void kernel_launch(void* const* d_in, const int* in_sizes, int n_in,
                              void* d_out, int out_size) {
    // Map inputs by unique element count (robust to ordering).
    const float *t1 = nullptr, *t2 = nullptr, *t3 = nullptr, *t4 = nullptr, *ff = nullptr;
    for (int i = 0; i < n_in; i++) {
        switch (in_sizes[i]) {
            case 8*128*56*56:   t1 = (const float*)d_in[i]; break;   // 3211264
            case 8*64*112*112:  t2 = (const float*)d_in[i]; break;   // 6422528
            case 8*32*224*224:  t3 = (const float*)d_in[i]; break;   // 12845056
            case 8*16*448*448:  t4 = (const float*)d_in[i]; break;   // 25690112
            case 8*256*28*28:   ff = (const float*)d_in[i]; break;   // 1605632
        }
    }

    fused_pool_kernel<<<POOL_BLOCKS, 256>>>(t1, t2, t3, t4);

    constexpr int HALF4 = (NB * 256 * PLANE4) / 2;   // 200704
    constexpr int CB = HALF4 / 256;                   // 784 blocks, exact

    // Launch combine with Programmatic Dependent Launch: blocks dispatch as
    // pool blocks retire; gridsync enforces the data dependency.
    cudaLaunchConfig_t cfg = {};
    cfg.gridDim  = dim3(CB, 1, 1);
    cfg.blockDim = dim3(256, 1, 1);
    cfg.dynamicSmemBytes = 0;
    cfg.stream = 0;   // same (capture) stream as the pool launch
    cudaLaunchAttribute attrs[1];
    attrs[0].id = cudaLaunchAttributeProgrammaticStreamSerialization;
    attrs[0].val.programmaticStreamSerializationAllowed = 1;
    cfg.attrs = attrs;
    cfg.numAttrs = 1;

    cudaError_t err = cudaLaunchKernelEx(&cfg, combine_kernel,
                                         ff, (float*)d_out);
    if (err != cudaSuccess) {
        // Fallback: plain stream-ordered launch (R11 behavior).
        combine_kernel<<<CB, 256>>>(ff, (float*)d_out);
    }
}

// round 17
// speedup vs baseline: 1.7457x; 1.2857x over previous
#include <cuda_runtime.h>
#include <math_constants.h>

// Output spatial: 28x28, batch 8, out channels 256.
#define HW   28
#define NB   8
#define PLANE (HW*HW)        // 784
#define PLANE4 (PLANE/4)     // 196

// Pooled scratch (channel-tiling means we pool once, reuse across replicas).
__device__ float g_p1[NB*128*PLANE]; // pool2  of (8,128,56,56)
__device__ float g_p2[NB*64 *PLANE]; // pool4  of (8,64,112,112)
__device__ float g_p3[NB*32 *PLANE]; // pool8  of (8,32,224,224)
__device__ float g_p4[NB*16 *PLANE]; // pool16 of (8,16,448,448)

// Block-range dispatch (256 threads/block). All requests lane-contiguous
// (100% sector efficiency); MLP=4 front-batched loads in A/C/D.
#define A_BLOCKS 6272    // k=16, t4, warp/2 outputs, 4 loads (64B runs)
#define B_BLOCKS 6272    // k=8,  t3, warp/4 outputs, 2 loads (32B runs)
#define C_BLOCKS 1568    // k=4,  t2, thread/output, 4 row-loads
#define D_BLOCKS 784     // k=2,  t1, thread/2x2 outputs, 4 row-loads
#define E_BLOCKS 196     // L2 prefetch of ff (one 128B line per thread)
#define POOL_BLOCKS (A_BLOCKS + B_BLOCKS + C_BLOCKS + D_BLOCKS + E_BLOCKS)

__device__ __forceinline__ float max4(float4 v) {
    return fmaxf(fmaxf(v.x, v.y), fmaxf(v.z, v.w));
}

__global__ void __launch_bounds__(256) fused_pool_kernel(
    const float* __restrict__ t1, const float* __restrict__ t2,
    const float* __restrict__ t3, const float* __restrict__ t4,
    const float* __restrict__ ff)
{
    int bid = blockIdx.x;
    int tid = threadIdx.x;

    if (bid < A_BLOCKS) {
        // ---- k=16 pool of (8,16,448,448): warp per 2 adjacent outputs ----
        // Outputs o0=2*warp, o0+1 share the output row (w even, w+1<28).
        // Lane l: 16B chunk (l&3) of rows (l>>2), (l>>2)+8, for both outputs.
        // 4 front-batched loads, each a 64B-dense lane-contiguous run.
        int t = bid * 256 + tid;
        int o0 = (t >> 5) * 2;                    // 0..100350, even
        int lane = t & 31;
        int r  = lane >> 2;                       // 0..7
        int ch = lane & 3;                        // 0..3
        int w = o0 % HW;                          // even
        int h = (o0 / HW) % HW;
        long bc = o0 / PLANE;                     // b*16 + c
        const float* base = t4 + (bc * 448 + (long)(h * 16 + r)) * 448
                               + (long)w * 16 + ch * 4;
        float4 v0 = __ldcs(reinterpret_cast<const float4*>(base));            // o0 r
        float4 v1 = __ldcs(reinterpret_cast<const float4*>(base + 8L * 448)); // o0 r+8
        float4 v2 = __ldcs(reinterpret_cast<const float4*>(base + 16));       // o0+1 r
        float4 v3 = __ldcs(reinterpret_cast<const float4*>(base + 16 + 8L * 448));
        float m0 = fmaxf(max4(v0), max4(v1));
        float m1 = fmaxf(max4(v2), max4(v3));
        #pragma unroll
        for (int k = 16; k >= 1; k >>= 1) {
            m0 = fmaxf(m0, __shfl_xor_sync(0xffffffffu, m0, k));
            m1 = fmaxf(m1, __shfl_xor_sync(0xffffffffu, m1, k));
        }
        if (lane == 0) {
            g_p4[o0]     = m0;
            g_p4[o0 + 1] = m1;
        }
        return;
    }
    bid -= A_BLOCKS;

    if (bid < B_BLOCKS) {
        // ---- k=8 pool of (8,32,224,224): warp covers 4 outputs ----
        int t = bid * 256 + tid;
        int obase = (t >> 5) * 4;                 // multiple of 4
        int lane = t & 31;
        int h2 = lane >> 4;                       // 0 or 1
        int ll = lane & 15;
        int r  = ll >> 1;                         // 0..7
        int ch = ll & 1;                          // 0..1
        int o0 = obase + h2;                      // second output is o0+2
        int w = o0 % HW;                          // 28 % 4 == 0: shared h,bc
        int h = (o0 / HW) % HW;
        long bc = o0 / PLANE;                     // b*32 + c
        const float* base = t3 + (bc * 224 + (long)(h * 8 + r)) * 224
                               + (long)w * 8 + ch * 4;
        float4 v0 = __ldcs(reinterpret_cast<const float4*>(base));       // o0
        float4 v1 = __ldcs(reinterpret_cast<const float4*>(base + 16));  // o0+2
        float m0 = max4(v0);
        float m1 = max4(v1);
        #pragma unroll
        for (int k = 8; k >= 1; k >>= 1) {        // reduce within 16-lane group
            m0 = fmaxf(m0, __shfl_xor_sync(0xffffffffu, m0, k));
            m1 = fmaxf(m1, __shfl_xor_sync(0xffffffffu, m1, k));
        }
        if (ll == 0) {
            g_p3[o0]     = m0;
            g_p3[o0 + 2] = m1;
        }
        return;
    }
    bid -= B_BLOCKS;

    if (bid < C_BLOCKS) {
        // ---- k=4 pool of (8,64,112,112): thread per output, 4 row-loads ----
        int oidx = bid * 256 + tid;               // 0..401407
        int w = oidx % HW;
        int h = (oidx / HW) % HW;
        long bc = oidx / PLANE;                   // b*64 + c
        const float* p = t2 + (bc * 112 + (long)(h * 4)) * 112 + (long)w * 4;
        float4 v0 = __ldcs(reinterpret_cast<const float4*>(p));
        float4 v1 = __ldcs(reinterpret_cast<const float4*>(p + 112));
        float4 v2 = __ldcs(reinterpret_cast<const float4*>(p + 224));
        float4 v3 = __ldcs(reinterpret_cast<const float4*>(p + 336));
        g_p2[oidx] = fmaxf(fmaxf(max4(v0), max4(v1)), fmaxf(max4(v2), max4(v3)));
        return;
    }
    bid -= C_BLOCKS;

    if (bid < D_BLOCKS) {
        // ---- k=2 pool of (8,128,56,56): thread per 2x2 output block ----
        // 4 input rows x 4 cols -> 4 outputs. Lanes contiguous in-row (16B).
        int t = bid * 256 + tid;                  // 0..200703
        constexpr int QROW = HW / 2;              // 14 blocks per output row
        constexpr int QPLANE = QROW * QROW;       // 196 blocks per plane
        int s  = t % QPLANE;
        int w2 = s % QROW;                        // 0..13
        int h4 = s / QROW;                        // 0..13
        long bc = t / QPLANE;                     // b*128 + c
        const float* p = t1 + (bc * 56 + (long)(h4 * 4)) * 56 + (long)w2 * 4;
        float4 r0 = __ldcs(reinterpret_cast<const float4*>(p));
        float4 r1 = __ldcs(reinterpret_cast<const float4*>(p + 56));
        float4 r2 = __ldcs(reinterpret_cast<const float4*>(p + 112));
        float4 r3 = __ldcs(reinterpret_cast<const float4*>(p + 168));
        float2 oa, ob;                            // output rows 2*h4, 2*h4+1
        oa.x = fmaxf(fmaxf(r0.x, r0.y), fmaxf(r1.x, r1.y));
        oa.y = fmaxf(fmaxf(r0.z, r0.w), fmaxf(r1.z, r1.w));
        ob.x = fmaxf(fmaxf(r2.x, r2.y), fmaxf(r3.x, r3.y));
        ob.y = fmaxf(fmaxf(r2.z, r2.w), fmaxf(r3.z, r3.w));
        float* q = g_p1 + bc * PLANE + (long)(h4 * 2) * HW + w2 * 2;
        *reinterpret_cast<float2*>(q)      = oa;
        *reinterpret_cast<float2*>(q + HW) = ob;
        return;
    }
    bid -= D_BLOCKS;

    {
        // ---- ff L2 prefetch: one 128B line per thread (exactly covers ff) ----
        int t = bid * 256 + tid;                  // 0..50175
        const float* p = ff + (long)t * 32;       // 50176*32 = 1605632 floats
        asm volatile("prefetch.global.L2 [%0];" :: "l"(p));
    }
}

__global__ void __launch_bounds__(256) combine_kernel(
    const float* __restrict__ ff, float* __restrict__ out)
{
    constexpr int TOTAL4 = NB * 256 * PLANE4;   // 401408
    constexpr int HALF4  = TOTAL4 / 2;          // 200704 (= 4 batches worth)
    int idx4 = blockIdx.x * blockDim.x + threadIdx.x;   // grid covers HALF4

    int s = idx4 % PLANE4;
    int c = (idx4 / PLANE4) % 256;
    int b = idx4 / (PLANE4 * 256);              // 0..3; second element is b+4

    const float4* P1 = reinterpret_cast<const float4*>(g_p1);
    const float4* P2 = reinterpret_cast<const float4*>(g_p2);
    const float4* P3 = reinterpret_cast<const float4*>(g_p3);
    const float4* P4 = reinterpret_cast<const float4*>(g_p4);
    const float4* FF = reinterpret_cast<const float4*>(ff);

    int i1 = (b * 128 + (c & 127)) * PLANE4 + s;
    int i2 = (b * 64  + (c & 63))  * PLANE4 + s;
    int i3 = (b * 32  + (c & 31))  * PLANE4 + s;
    int i4 = (b * 16  + (c & 15))  * PLANE4 + s;

    // Front-batch all 10 loads (2 output elements: batches b and b+4).
    float4 a0 = P1[i1],  a1 = P1[i1 + 4*128*PLANE4];
    float4 d0 = P2[i2],  d1 = P2[i2 + 4*64 *PLANE4];
    float4 e0 = P3[i3],  e1 = P3[i3 + 4*32 *PLANE4];
    float4 g0 = P4[i4],  g1 = P4[i4 + 4*16 *PLANE4];
    float4 f0 = FF[idx4], f1 = FF[idx4 + HALF4];

    float4 o0, o1;
    o0.x = fmaxf(a0.x + d0.x + e0.x + g0.x + f0.x, 0.0f);
    o0.y = fmaxf(a0.y + d0.y + e0.y + g0.y + f0.y, 0.0f);
    o0.z = fmaxf(a0.z + d0.z + e0.z + g0.z + f0.z, 0.0f);
    o0.w = fmaxf(a0.w + d0.w + e0.w + g0.w + f0.w, 0.0f);
    o1.x = fmaxf(a1.x + d1.x + e1.x + g1.x + f1.x, 0.0f);
    o1.y = fmaxf(a1.y + d1.y + e1.y + g1.y + f1.y, 0.0f);
    o1.z = fmaxf(a1.z + d1.z + e1.z + g1.z + f1.z, 0.0f);
    o1.w = fmaxf(a1.w + d1.w + e1.w + g1.w + f1.w, 0.0f);
    reinterpret_cast<float4*>(out)[idx4] = o0;
    reinterpret_cast<float4*>(out)[idx4 + HALF4] = o1;
}

extern "C" void kernel_launch(void* const* d_in, const int* in_sizes, int n_in,
                              void* d_out, int out_size) {
    // Map inputs by unique element count (robust to ordering).
    const float *t1 = nullptr, *t2 = nullptr, *t3 = nullptr, *t4 = nullptr, *ff = nullptr;
    for (int i = 0; i < n_in; i++) {
        switch (in_sizes[i]) {
            case 8*128*56*56:   t1 = (const float*)d_in[i]; break;   // 3211264
            case 8*64*112*112:  t2 = (const float*)d_in[i]; break;   // 6422528
            case 8*32*224*224:  t3 = (const float*)d_in[i]; break;   // 12845056
            case 8*16*448*448:  t4 = (const float*)d_in[i]; break;   // 25690112
            case 8*256*28*28:   ff = (const float*)d_in[i]; break;   // 1605632
        }
    }

    fused_pool_kernel<<<POOL_BLOCKS, 256>>>(t1, t2, t3, t4, ff);

    constexpr int HALF4 = (NB * 256 * PLANE4) / 2;   // 200704
    combine_kernel<<<HALF4 / 256, 256>>>(ff, (float*)d_out);
}